// round 15
// baseline (speedup 1.0000x reference)
#include <cuda_runtime.h>
#include <math_constants.h>

#define IN_DIM   256
#define CODE_LEN 128
#define MEM_LEN  65536
#define NT       256
#define GRID     888                 // 148 SMs * 6 CTAs — exactly one resident wave

#define N_MD  (MEM_LEN * IN_DIM)     // 16777216 floats
#define N_MEM (MEM_LEN * CODE_LEN)   //  8388608 floats
#define S_MD  ((N_MD  - 7) / 4 + 1)  // 4194303 aligned slots (out+3 base)
#define S_MEM ((N_MEM - 7) / 4 + 1)  // 2097151 aligned slots

// Work-stealing chunking
#define MD_CHUNKS   4096             // 1024 slots each (2 x 512-slot block units)
#define MEM_CHUNKS  (MEM_LEN / 16)   // 4096 chunks of 16 rows

// Output layout (flattened tuple, all f32):
#define OUT_MEM_OFF 1LL
#define OUT_MD_OFF  (1LL + (long long)N_MEM)
#define OUT_IDX_OFF (OUT_MD_OFF + (long long)N_MD)

// Scratch (device globals; statically armed, re-armed by the final block)
__device__ float               g_colsum[IN_DIM];                  // zero-init
__device__ float               g_colsq[IN_DIM];                   // zero-init
__device__ __align__(16) float g_enc[CODE_LEN];
__device__ int                 g_minbits = 0x7f800000;            // +inf
__device__ unsigned long long  g_argmin  = 0xFFFFFFFFFFFFFFFFULL;
__device__ unsigned            g_ticket  = 0;
__device__ unsigned            g_sdone   = 0;                     // blocks past P1
__device__ unsigned            g_encdone = 0;                     // enc rows done
__device__ unsigned            g_cmd     = 0;                     // md chunk counter
__device__ unsigned            g_cmem    = 0;                     // mem chunk counter

#define FULL 0xFFFFFFFFu

__global__ void __launch_bounds__(NT, 6)
fused(const float* __restrict__ md_f,  float* __restrict__ out_md,
      const float* __restrict__ mem_f, float* __restrict__ out_mem,
      const int* __restrict__ idx,     float* __restrict__ out_idx,
      const float* __restrict__ x,     const float* __restrict__ W,
      const float* __restrict__ bias,  const int* __restrict__ count,
      float* __restrict__ out) {
    const float4* md4   = (const float4*)md_f;
    const float4* mem4  = (const float4*)mem_f;
    float4*       o4md  = (float4*)(out_md + 3);       // 16B-aligned
    float4*       o4mem = (float4*)(out_mem + 3);      // 16B-aligned
    const int tid  = threadIdx.x;
    const int lane = tid & 31;
    const int wid  = tid >> 5;

    __shared__ float sW[IN_DIM];
    if (blockIdx.x < CODE_LEN) sW[tid] = W[blockIdx.x * IN_DIM + tid];

    __shared__ int s_c;

    // ================= P1: mem_data stats + realigned copy (stolen) ========
    // Chunk c covers slots [c*1024, (c+1)*1024): two 512-slot units; in each,
    // warp-pair tiling: warp covers {wofs..wofs+31} U {wofs+64..wofs+95}.
    float s0 = 0, s1 = 0, s2 = 0, s3 = 0;
    float q0 = 0, q1 = 0, q2 = 0, q3 = 0;
    const unsigned wofs = (unsigned)(wid >> 1) * 128u + (unsigned)(wid & 1) * 32u;

    for (;;) {
        if (tid == 0) s_c = (int)atomicAdd(&g_cmd, 1u);
        __syncthreads();
        int c = s_c;
        __syncthreads();
        if (c >= MD_CHUNKS) break;
        #pragma unroll
        for (int k = 0; k < 2; k++) {
            unsigned wb = (unsigned)c * 1024u + (unsigned)k * 512u + wofs;
            unsigned k1 = wb + lane;
            unsigned k2 = k1 + 64u;
            bool ok1 = k1 < S_MD;
            bool ok2 = k2 < S_MD;
            float4 v1 = ok1 ? __ldcs(md4 + k1 + 1) : make_float4(0.f, 0.f, 0.f, 0.f);
            float4 v2 = ok2 ? __ldcs(md4 + k2 + 1) : make_float4(0.f, 0.f, 0.f, 0.f);
            float pw1 = __shfl_up_sync(FULL, v1.w, 1);
            float pw2 = __shfl_up_sync(FULL, v2.w, 1);
            if (lane == 0) {
                pw1 = md_f[4u * wb + 3u];
                if (wb + 64u < S_MD) pw2 = md_f[4u * (wb + 64u) + 3u];
            }
            if (ok1) __stcs(o4md + k1, make_float4(pw1, v1.x, v1.y, v1.z));
            if (ok2) __stcs(o4md + k2, make_float4(pw2, v2.x, v2.y, v2.z));
            s0 += v1.x + v2.x; q0 += v1.x * v1.x + v2.x * v2.x;
            s1 += v1.y + v2.y; q1 += v1.y * v1.y + v2.y * v2.y;
            s2 += v1.z + v2.z; q2 += v1.z * v1.z + v2.z * v2.z;
            s3 += v1.w + v2.w; q3 += v1.w * v1.w + v2.w * v2.w;
        }
    }

    // Block reduce: column of this thread is fixed across all stolen chunks
    // (chunk stride 1024 ≡ 0 mod 64 in slots; element col = (4*(wofs%64 + lane)+4) & 255).
    int col = (int)((4u * ((unsigned)(wid & 1) * 32u + (unsigned)lane) + 4u) & 255u);
    {
        __shared__ float sh_s[8][IN_DIM];
        __shared__ float sh_q[8][IN_DIM];
        #pragma unroll
        for (int j = 0; j < 8; j++) { sh_s[j][tid] = 0.f; sh_q[j][tid] = 0.f; }
        __syncthreads();
        sh_s[wid][col] = s0; sh_s[wid][col + 1] = s1; sh_s[wid][col + 2] = s2; sh_s[wid][col + 3] = s3;
        sh_q[wid][col] = q0; sh_q[wid][col + 1] = q1; sh_q[wid][col + 2] = q2; sh_q[wid][col + 3] = q3;
        __syncthreads();
        float ts = 0.f, tq = 0.f;
        #pragma unroll
        for (int j = 0; j < 8; j++) { ts += sh_s[j][tid]; tq += sh_q[j][tid]; }
        atomicAdd(&g_colsum[tid], ts);
        atomicAdd(&g_colsq[tid],  tq);
    }

    // mem_idx copy + packed argmin (blocks 0..255 dense)
    {
        int gtid = blockIdx.x * NT + tid;
        if (gtid < MEM_LEN) {
            int v = idx[gtid];
            out_idx[gtid] = (float)v;
            unsigned long long key =
                ((unsigned long long)(unsigned)(v ^ 0x80000000) << 32) | (unsigned long long)gtid;
            #pragma unroll
            for (int off = 16; off; off >>= 1) {
                unsigned long long o = __shfl_xor_sync(FULL, key, off);
                key = (o < key) ? o : key;
            }
            if (lane == 0) atomicMin(&g_argmin, key);
        }
    }

    // Head/tail elements + stats for input elements 0..3
    if (blockIdx.x == 0 && tid == 0) {
        out_md[0] = md_f[0]; out_md[1] = md_f[1]; out_md[2] = md_f[2];
        out_md[N_MD - 1] = md_f[N_MD - 1];
        out_mem[0] = mem_f[0]; out_mem[1] = mem_f[1]; out_mem[2] = mem_f[2];
        out_mem[N_MEM - 1] = mem_f[N_MEM - 1];
        #pragma unroll
        for (int j = 0; j < 4; j++) {
            float v = md_f[j];
            atomicAdd(&g_colsum[j], v);
            atomicAdd(&g_colsq[j],  v * v);
        }
    }

    __threadfence();
    __syncthreads();
    if (tid == 0) atomicAdd(&g_sdone, 1u);

    // ================= P2: enc (blocks 0..127) =============================
    if (blockIdx.x < CODE_LEN) {
        if (tid == 0) {
            while (*(volatile unsigned*)&g_sdone < (unsigned)GRID) __nanosleep(32);
        }
        __syncthreads();
        __threadfence();   // acquire all col stats
        float mean = g_colsum[tid] * (1.0f / (float)MEM_LEN);
        float var  = (g_colsq[tid] - (float)MEM_LEN * mean * mean) * (1.0f / (float)(MEM_LEN - 1));
        float sd   = sqrtf(fmaxf(var, 0.0f));
        float nv   = (sd == 0.0f) ? 0.0f : (x[tid] - mean) / sd;
        float p    = nv * sW[tid];
        #pragma unroll
        for (int off = 16; off; off >>= 1) p += __shfl_xor_sync(FULL, p, off);
        __shared__ float red[8];
        if (lane == 0) red[wid] = p;
        __syncthreads();
        if (tid == 0) {
            float a = bias[blockIdx.x];
            #pragma unroll
            for (int i = 0; i < 8; i++) a += red[i];
            g_enc[blockIdx.x] = a;
            __threadfence();
            atomicAdd(&g_encdone, 1u);
        }
    }

    // ================= P3: memory — FUSED copy + L1 distance (stolen) ======
    if (tid == 0) {
        while (*(volatile unsigned*)&g_encdone < (unsigned)CODE_LEN) __nanosleep(32);
    }
    __syncthreads();
    __threadfence();   // acquire g_enc

    {
        const float4 e = ((const float4*)g_enc)[lane];   // 4 regs/lane
        float best = CUDART_INF_F;

        for (;;) {
            if (tid == 0) s_c = (int)atomicAdd(&g_cmem, 1u);
            __syncthreads();
            int c = s_c;
            __syncthreads();
            if (c >= MEM_CHUNKS) break;
            int r1 = c * 16 + wid * 2;                   // warp owns rows r1, r1+1
            int r2 = r1 + 1;
            float4 va = __ldcs(mem4 + (unsigned)r1 * 32u + lane);
            float4 vb = __ldcs(mem4 + (unsigned)r2 * 32u + lane);
            // realigned copy: slot i-1 = {prev elem .w, my .xyz}
            float pa = __shfl_up_sync(FULL, va.w, 1);
            float pb = __shfl_up_sync(FULL, vb.w, 1);
            if (lane == 0) {
                // element before float4 index r*32 is mem_f[r*128 - 1]
                if (r1 > 0) pa = mem_f[(unsigned)r1 * 128u - 1u];
                pb = mem_f[(unsigned)r2 * 128u - 1u];
            }
            if (lane > 0 || r1 > 0)
                __stcs(o4mem + (unsigned)r1 * 32u + lane - 1u, make_float4(pa, va.x, va.y, va.z));
            __stcs(o4mem + (unsigned)r2 * 32u + lane - 1u, make_float4(pb, vb.x, vb.y, vb.z));
            // L1 distances
            float d1 = fabsf(va.x - e.x) + fabsf(va.y - e.y) + fabsf(va.z - e.z) + fabsf(va.w - e.w);
            float d2 = fabsf(vb.x - e.x) + fabsf(vb.y - e.y) + fabsf(vb.z - e.z) + fabsf(vb.w - e.w);
            #pragma unroll
            for (int off = 16; off; off >>= 1) {
                d1 += __shfl_xor_sync(FULL, d1, off);
                d2 += __shfl_xor_sync(FULL, d2, off);
            }
            best = fminf(best, fminf(d1, d2));
        }

        // block-level min staging: ONE global atomic per block
        __shared__ float smin[8];
        if (lane == 0) smin[wid] = best;
        __syncthreads();
        if (tid == 0) {
            float mm = smin[0];
            #pragma unroll
            for (int j = 1; j < 8; j++) mm = fminf(mm, smin[j]);
            atomicMin(&g_minbits, __float_as_int(mm));
        }
    }

    // ================= P4: last-block final + re-arm =======================
    __threadfence();
    __syncthreads();
    __shared__ int s_last;
    if (tid == 0) s_last = (atomicAdd(&g_ticket, 1) == GRID - 1) ? 1 : 0;
    __syncthreads();
    if (s_last) {
        float loss = __int_as_float(atomicAdd(&g_minbits, 0));
        unsigned long long am = atomicAdd(&g_argmin, 0ULL);
        long long pos = (long long)(unsigned)(am & 0xFFFFFFFFULL);
        if (tid == 0) out[0] = loss;
        if (loss <= 1.0f) {
            if (tid < CODE_LEN) out[OUT_MEM_OFF + pos * CODE_LEN + tid] = g_enc[tid];
            out[OUT_MD_OFF + pos * IN_DIM + tid] = x[tid];
            if (tid == 0) out[OUT_IDX_OFF + pos] = (float)count[0];
        }
        __syncthreads();                 // done reading accumulators
        g_colsum[tid] = 0.0f;            // re-arm for next graph replay
        g_colsq[tid]  = 0.0f;
        if (tid == 0) {
            g_minbits = 0x7f800000;
            g_argmin  = 0xFFFFFFFFFFFFFFFFULL;
            g_ticket  = 0;
            g_sdone   = 0;
            g_encdone = 0;
            g_cmd     = 0;
            g_cmem    = 0;
        }
    }
}

// ---------------------------------------------------------------------------
extern "C" void kernel_launch(void* const* d_in, const int* in_sizes, int n_in,
                              void* d_out, int out_size) {
    const float* x        = (const float*)d_in[0];
    const float* memory   = (const float*)d_in[1];
    const float* mem_data = (const float*)d_in[2];
    const int*   mem_idx  = (const int*)d_in[3];
    const float* W        = (const float*)d_in[4];
    const float* b        = (const float*)d_in[5];
    const int*   count    = (const int*)d_in[6];
    float* out = (float*)d_out;

    fused<<<GRID, NT>>>(mem_data, out + OUT_MD_OFF,
                        memory,   out + OUT_MEM_OFF,
                        mem_idx,  out + OUT_IDX_OFF,
                        x, W, b, count, out);
}

// round 16
// speedup vs baseline: 1.0006x; 1.0006x over previous
#include <cuda_runtime.h>
#include <math_constants.h>

#define IN_DIM   256
#define CODE_LEN 128
#define MEM_LEN  65536
#define NT       256
#define GRID     888                 // 148 SMs * 6 CTAs — exactly one resident wave

#define N_MD  (MEM_LEN * IN_DIM)     // 16777216 floats
#define N_MEM (MEM_LEN * CODE_LEN)   //  8388608 floats
#define S_MD  ((N_MD  - 7) / 4 + 1)  // 4194303 aligned slots (out+3 base)
#define S_MEM ((N_MEM - 7) / 4 + 1)  // 2097151 aligned slots

// Unified task queue: 4096 md-chunks + 2048 mem-chunks, 1024 slots each,
// interleaved 2:1 (t%3==2 -> mem chunk) so both streams run concurrently.
#define N_TASKS     6144
#define DIST_CHUNKS (MEM_LEN / 16)   // 4096 chunks of 16 rows

// Output layout (flattened tuple, all f32):
#define OUT_MEM_OFF 1LL
#define OUT_MD_OFF  (1LL + (long long)N_MEM)
#define OUT_IDX_OFF (OUT_MD_OFF + (long long)N_MD)

// Scratch (device globals; statically armed, re-armed by the final block)
__device__ float               g_colsum[IN_DIM];                  // zero-init
__device__ float               g_colsq[IN_DIM];                   // zero-init
__device__ __align__(16) float g_enc[CODE_LEN];
__device__ int                 g_minbits = 0x7f800000;            // +inf
__device__ unsigned long long  g_argmin  = 0xFFFFFFFFFFFFFFFFULL;
__device__ unsigned            g_ticket  = 0;
__device__ unsigned            g_sdone   = 0;                     // blocks past streaming
__device__ unsigned            g_encdone = 0;                     // enc rows done
__device__ unsigned            g_ctask   = 0;                     // unified task counter
__device__ unsigned            g_cdist   = 0;                     // dist chunk counter

#define FULL 0xFFFFFFFFu

__global__ void __launch_bounds__(NT, 6)
fused(const float* __restrict__ md_f,  float* __restrict__ out_md,
      const float* __restrict__ mem_f, float* __restrict__ out_mem,
      const int* __restrict__ idx,     float* __restrict__ out_idx,
      const float* __restrict__ x,     const float* __restrict__ W,
      const float* __restrict__ bias,  const int* __restrict__ count,
      float* __restrict__ out) {
    const float4* md4   = (const float4*)md_f;
    const float4* mem4  = (const float4*)mem_f;
    float4*       o4md  = (float4*)(out_md + 3);       // 16B-aligned
    float4*       o4mem = (float4*)(out_mem + 3);      // 16B-aligned
    const int tid  = threadIdx.x;
    const int lane = tid & 31;
    const int wid  = tid >> 5;

    __shared__ float sW[IN_DIM];
    if (blockIdx.x < CODE_LEN) sW[tid] = W[blockIdx.x * IN_DIM + tid];

    __shared__ int s_c;

    // ============ P1: unified stolen streaming (both arrays) ===============
    // Warp-pair tiling inside a 1024-slot chunk: warp covers
    // {wofs..wofs+31} U {wofs+64..wofs+95} in each of two 512-slot units.
    float s0 = 0, s1 = 0, s2 = 0, s3 = 0;
    float q0 = 0, q1 = 0, q2 = 0, q3 = 0;
    const unsigned wofs = (unsigned)(wid >> 1) * 128u + (unsigned)(wid & 1) * 32u;

    for (;;) {
        if (tid == 0) s_c = (int)atomicAdd(&g_ctask, 1u);
        __syncthreads();
        int t = s_c;
        __syncthreads();
        if (t >= N_TASKS) break;

        if ((t % 3) != 2) {
            // ---- mem_data chunk: stats + realigned copy (evict-first) ----
            unsigned c = (unsigned)(t / 3) * 2u + (unsigned)(t % 3);   // 0..4095
            #pragma unroll
            for (int k = 0; k < 2; k++) {
                unsigned wb = c * 1024u + (unsigned)k * 512u + wofs;
                unsigned k1 = wb + lane;
                unsigned k2 = k1 + 64u;
                bool ok1 = k1 < S_MD;
                bool ok2 = k2 < S_MD;
                float4 v1 = ok1 ? __ldcs(md4 + k1 + 1) : make_float4(0.f, 0.f, 0.f, 0.f);
                float4 v2 = ok2 ? __ldcs(md4 + k2 + 1) : make_float4(0.f, 0.f, 0.f, 0.f);
                float pw1 = __shfl_up_sync(FULL, v1.w, 1);
                float pw2 = __shfl_up_sync(FULL, v2.w, 1);
                if (lane == 0) {
                    pw1 = md_f[4u * wb + 3u];
                    if (wb + 64u < S_MD) pw2 = md_f[4u * (wb + 64u) + 3u];
                }
                if (ok1) __stcs(o4md + k1, make_float4(pw1, v1.x, v1.y, v1.z));
                if (ok2) __stcs(o4md + k2, make_float4(pw2, v2.x, v2.y, v2.z));
                s0 += v1.x + v2.x; q0 += v1.x * v1.x + v2.x * v2.x;
                s1 += v1.y + v2.y; q1 += v1.y * v1.y + v2.y * v2.y;
                s2 += v1.z + v2.z; q2 += v1.z * v1.z + v2.z * v2.z;
                s3 += v1.w + v2.w; q3 += v1.w * v1.w + v2.w * v2.w;
            }
        } else {
            // ---- memory chunk: realigned copy (reads default -> L2-kept) --
            unsigned c = (unsigned)(t / 3);                            // 0..2047
            #pragma unroll
            for (int k = 0; k < 2; k++) {
                unsigned wb = c * 1024u + (unsigned)k * 512u + wofs;
                unsigned k1 = wb + lane;
                unsigned k2 = k1 + 64u;
                bool ok1 = k1 < S_MEM;
                bool ok2 = k2 < S_MEM;
                float4 v1 = ok1 ? mem4[k1 + 1] : make_float4(0.f, 0.f, 0.f, 0.f);
                float4 v2 = ok2 ? mem4[k2 + 1] : make_float4(0.f, 0.f, 0.f, 0.f);
                float pw1 = __shfl_up_sync(FULL, v1.w, 1);
                float pw2 = __shfl_up_sync(FULL, v2.w, 1);
                if (lane == 0) {
                    pw1 = mem_f[4u * wb + 3u];
                    if (wb + 64u < S_MEM) pw2 = mem_f[4u * (wb + 64u) + 3u];
                }
                if (ok1) __stcs(o4mem + k1, make_float4(pw1, v1.x, v1.y, v1.z));
                if (ok2) __stcs(o4mem + k2, make_float4(pw2, v2.x, v2.y, v2.z));
            }
        }
    }

    // Block reduce: this thread's element column is fixed across all chunks
    // (chunk base 1024 ≡ 0 mod 64 slots).
    int col = (int)((4u * ((unsigned)(wid & 1) * 32u + (unsigned)lane) + 4u) & 255u);
    {
        __shared__ float sh_s[8][IN_DIM];
        __shared__ float sh_q[8][IN_DIM];
        #pragma unroll
        for (int j = 0; j < 8; j++) { sh_s[j][tid] = 0.f; sh_q[j][tid] = 0.f; }
        __syncthreads();
        sh_s[wid][col] = s0; sh_s[wid][col + 1] = s1; sh_s[wid][col + 2] = s2; sh_s[wid][col + 3] = s3;
        sh_q[wid][col] = q0; sh_q[wid][col + 1] = q1; sh_q[wid][col + 2] = q2; sh_q[wid][col + 3] = q3;
        __syncthreads();
        float ts = 0.f, tq = 0.f;
        #pragma unroll
        for (int j = 0; j < 8; j++) { ts += sh_s[j][tid]; tq += sh_q[j][tid]; }
        atomicAdd(&g_colsum[tid], ts);
        atomicAdd(&g_colsq[tid],  tq);
    }

    // mem_idx copy + packed argmin (blocks 0..255 dense)
    {
        int gtid = blockIdx.x * NT + tid;
        if (gtid < MEM_LEN) {
            int v = idx[gtid];
            out_idx[gtid] = (float)v;
            unsigned long long key =
                ((unsigned long long)(unsigned)(v ^ 0x80000000) << 32) | (unsigned long long)gtid;
            #pragma unroll
            for (int off = 16; off; off >>= 1) {
                unsigned long long o = __shfl_xor_sync(FULL, key, off);
                key = (o < key) ? o : key;
            }
            if (lane == 0) atomicMin(&g_argmin, key);
        }
    }

    // Head/tail elements + stats for input elements 0..3
    if (blockIdx.x == 0 && tid == 0) {
        out_md[0] = md_f[0]; out_md[1] = md_f[1]; out_md[2] = md_f[2];
        out_md[N_MD - 1] = md_f[N_MD - 1];
        out_mem[0] = mem_f[0]; out_mem[1] = mem_f[1]; out_mem[2] = mem_f[2];
        out_mem[N_MEM - 1] = mem_f[N_MEM - 1];
        #pragma unroll
        for (int j = 0; j < 4; j++) {
            float v = md_f[j];
            atomicAdd(&g_colsum[j], v);
            atomicAdd(&g_colsq[j],  v * v);
        }
    }

    __threadfence();
    __syncthreads();
    if (tid == 0) atomicAdd(&g_sdone, 1u);

    // ================= P2: enc (blocks 0..127) =============================
    if (blockIdx.x < CODE_LEN) {
        if (tid == 0) {
            while (*(volatile unsigned*)&g_sdone < (unsigned)GRID) __nanosleep(32);
        }
        __syncthreads();
        __threadfence();   // acquire all col stats
        float mean = g_colsum[tid] * (1.0f / (float)MEM_LEN);
        float var  = (g_colsq[tid] - (float)MEM_LEN * mean * mean) * (1.0f / (float)(MEM_LEN - 1));
        float sd   = sqrtf(fmaxf(var, 0.0f));
        float nv   = (sd == 0.0f) ? 0.0f : (x[tid] - mean) / sd;
        float p    = nv * sW[tid];
        #pragma unroll
        for (int off = 16; off; off >>= 1) p += __shfl_xor_sync(FULL, p, off);
        __shared__ float red[8];
        if (lane == 0) red[wid] = p;
        __syncthreads();
        if (tid == 0) {
            float a = bias[blockIdx.x];
            #pragma unroll
            for (int i = 0; i < 8; i++) a += red[i];
            g_enc[blockIdx.x] = a;
            __threadfence();
            atomicAdd(&g_encdone, 1u);
        }
    }

    // ================= P3: stolen pure-read dist (L2-resident) =============
    if (tid == 0) {
        while (*(volatile unsigned*)&g_encdone < (unsigned)CODE_LEN) __nanosleep(32);
    }
    __syncthreads();
    __threadfence();   // acquire g_enc

    {
        const float4 e = ((const float4*)g_enc)[lane];   // 4 regs/lane
        float best = CUDART_INF_F;

        for (;;) {
            if (tid == 0) s_c = (int)atomicAdd(&g_cdist, 1u);
            __syncthreads();
            int c = s_c;
            __syncthreads();
            if (c >= DIST_CHUNKS) break;
            int r1 = c * 16 + wid * 2;                   // warp owns rows r1, r1+1
            int r2 = r1 + 1;
            float4 va = mem4[(unsigned)r1 * 32u + lane];
            float4 vb = mem4[(unsigned)r2 * 32u + lane];
            float d1 = fabsf(va.x - e.x) + fabsf(va.y - e.y) + fabsf(va.z - e.z) + fabsf(va.w - e.w);
            float d2 = fabsf(vb.x - e.x) + fabsf(vb.y - e.y) + fabsf(vb.z - e.z) + fabsf(vb.w - e.w);
            #pragma unroll
            for (int off = 16; off; off >>= 1) {
                d1 += __shfl_xor_sync(FULL, d1, off);
                d2 += __shfl_xor_sync(FULL, d2, off);
            }
            best = fminf(best, fminf(d1, d2));
        }

        // block-level min staging: ONE global atomic per block
        __shared__ float smin[8];
        if (lane == 0) smin[wid] = best;
        __syncthreads();
        if (tid == 0) {
            float mm = smin[0];
            #pragma unroll
            for (int j = 1; j < 8; j++) mm = fminf(mm, smin[j]);
            atomicMin(&g_minbits, __float_as_int(mm));
        }
    }

    // ================= P4: last-block final + re-arm =======================
    __threadfence();
    __syncthreads();
    __shared__ int s_last;
    if (tid == 0) s_last = (atomicAdd(&g_ticket, 1) == GRID - 1) ? 1 : 0;
    __syncthreads();
    if (s_last) {
        float loss = __int_as_float(atomicAdd(&g_minbits, 0));
        unsigned long long am = atomicAdd(&g_argmin, 0ULL);
        long long pos = (long long)(unsigned)(am & 0xFFFFFFFFULL);
        if (tid == 0) out[0] = loss;
        if (loss <= 1.0f) {
            if (tid < CODE_LEN) out[OUT_MEM_OFF + pos * CODE_LEN + tid] = g_enc[tid];
            out[OUT_MD_OFF + pos * IN_DIM + tid] = x[tid];
            if (tid == 0) out[OUT_IDX_OFF + pos] = (float)count[0];
        }
        __syncthreads();                 // done reading accumulators
        g_colsum[tid] = 0.0f;            // re-arm for next graph replay
        g_colsq[tid]  = 0.0f;
        if (tid == 0) {
            g_minbits = 0x7f800000;
            g_argmin  = 0xFFFFFFFFFFFFFFFFULL;
            g_ticket  = 0;
            g_sdone   = 0;
            g_encdone = 0;
            g_ctask   = 0;
            g_cdist   = 0;
        }
    }
}

// ---------------------------------------------------------------------------
extern "C" void kernel_launch(void* const* d_in, const int* in_sizes, int n_in,
                              void* d_out, int out_size) {
    const float* x        = (const float*)d_in[0];
    const float* memory   = (const float*)d_in[1];
    const float* mem_data = (const float*)d_in[2];
    const int*   mem_idx  = (const int*)d_in[3];
    const float* W        = (const float*)d_in[4];
    const float* b        = (const float*)d_in[5];
    const int*   count    = (const int*)d_in[6];
    float* out = (float*)d_out;

    fused<<<GRID, NT>>>(mem_data, out + OUT_MD_OFF,
                        memory,   out + OUT_MEM_OFF,
                        mem_idx,  out + OUT_IDX_OFF,
                        x, W, b, count, out);
}